// round 2
// baseline (speedup 1.0000x reference)
#include <cuda_runtime.h>
#include <math.h>

#define B_    8
#define N_    512
#define KN    128
#define ATOMS 4096      // B_*N_
#define DRDIM 1600
#define F0    240

// ---------------- scratch (no allocations allowed) ----------------
__device__ float g_DR[ATOMS * DRDIM];   // 26 MB
__device__ float g_H1[ATOMS * F0];
__device__ float g_H2[ATOMS * F0];
__device__ float g_H3[ATOMS * F0];

// fast, accurate-enough tanh: 1 - 2/(1+exp(2x)); abs err ~1e-7
__device__ __forceinline__ float tanhfast(float x) {
    float e = __expf(2.0f * x);
    return 1.0f - __fdividef(2.0f, e + 1.0f);
}

// ---------------- kernel 1: per-atom embedding + DR ----------------
// block = 1 atom, 128 threads = 128 neighbors
__global__ __launch_bounds__(128) void embed_kernel(
    const float4* __restrict__ img,
    const float* __restrict__ ew0, const float* __restrict__ eb0,
    const float* __restrict__ ew1, const float* __restrict__ eb1,
    const float* __restrict__ ew2, const float* __restrict__ eb2)
{
    __shared__ float s_w1[25 * 52];       // padded rows (50 -> 52) for float4 LDS
    __shared__ float s_w2[50 * 100];
    __shared__ float s_w0[25], s_b0[25], s_b1[52], s_b2[100];
    __shared__ float sRi[128 * 4];
    __shared__ float sG[128 * 21];        // 20 G-cols per chunk, pad 21
    __shared__ float sB[400];             // tmpB [4][100]

    const int tid = threadIdx.x;
    const int atom = blockIdx.x;

    // stage embedding weights into shared (broadcast-read later)
    for (int idx = tid; idx < 25 * 52; idx += 128) {
        int i = idx / 52, k = idx - i * 52;
        s_w1[idx] = (k < 50) ? ew1[i * 50 + k] : 0.0f;
    }
    for (int idx = tid; idx < 5000; idx += 128) s_w2[idx] = ew2[idx];
    if (tid < 25)  { s_w0[tid] = ew0[tid]; s_b0[tid] = eb0[tid]; }
    if (tid < 52)  s_b1[tid] = (tid < 50) ? eb1[tid] : 0.0f;
    if (tid < 100) s_b2[tid] = eb2[tid];

    // per-neighbor geometry
    float4 p = img[atom * KN + tid];
    float R = p.x * p.x + p.y * p.y + p.z * p.z;
    bool mask = p.w > 0.0f;
    float S = 0.0f;
    if (R < 10.0f) {
        if (mask) S = 1.0f / R;
    } else if (R < 25.0f) {
        // NOTE: reference's b2 branch does NOT require mask
        S = 0.5f * cosf(0.20943951023931953f * (R - 10.0f)) + 0.5f;
    }
    float coef = mask ? S / R : 0.0f;
    sRi[tid * 4 + 0] = S;
    sRi[tid * 4 + 1] = coef * p.x;
    sRi[tid * 4 + 2] = coef * p.y;
    sRi[tid * 4 + 3] = coef * p.z;
    __syncthreads();

    // layer 1: scalar -> 25
    float h1[25];
#pragma unroll
    for (int k = 0; k < 25; k++) h1[k] = tanhfast(fmaf(S, s_w0[k], s_b0[k]));

    // layer 2: 25 -> 50 (accumulate over padded 52)
    float acc[52];
#pragma unroll
    for (int k = 0; k < 52; k++) acc[k] = s_b1[k];
#pragma unroll
    for (int i = 0; i < 25; i++) {
        float a = h1[i];
        const float4* w4 = reinterpret_cast<const float4*>(&s_w1[i * 52]);
#pragma unroll
        for (int q = 0; q < 13; q++) {
            float4 w = w4[q];
            acc[q * 4 + 0] = fmaf(a, w.x, acc[q * 4 + 0]);
            acc[q * 4 + 1] = fmaf(a, w.y, acc[q * 4 + 1]);
            acc[q * 4 + 2] = fmaf(a, w.z, acc[q * 4 + 2]);
            acc[q * 4 + 3] = fmaf(a, w.w, acc[q * 4 + 3]);
        }
    }
    float h2[50];
#pragma unroll
    for (int k = 0; k < 50; k++) h2[k] = tanhfast(acc[k]);

    // layer 3 (50 -> 100) in 5 chunks of 20 columns; reduce tmpB after each
#pragma unroll 1
    for (int chunk = 0; chunk < 5; chunk++) {
        float g[20];
#pragma unroll
        for (int mm = 0; mm < 20; mm++) g[mm] = s_b2[chunk * 20 + mm];
#pragma unroll
        for (int i = 0; i < 50; i++) {
            float a = h2[i];
            const float4* w4 = reinterpret_cast<const float4*>(&s_w2[i * 100 + chunk * 20]);
#pragma unroll
            for (int q = 0; q < 5; q++) {
                float4 w = w4[q];
                g[q * 4 + 0] = fmaf(a, w.x, g[q * 4 + 0]);
                g[q * 4 + 1] = fmaf(a, w.y, g[q * 4 + 1]);
                g[q * 4 + 2] = fmaf(a, w.z, g[q * 4 + 2]);
                g[q * 4 + 3] = fmaf(a, w.w, g[q * 4 + 3]);
            }
        }
#pragma unroll
        for (int mm = 0; mm < 20; mm++) sG[tid * 21 + mm] = tanhfast(g[mm]);
        __syncthreads();

        // tmpB[f][chunk*20+c] = sum_j Ri[j][f] * G[j][c]
        if (tid < 80) {
            int f = tid / 20, c = tid - f * 20;
            float a0 = 0.0f;
#pragma unroll 4
            for (int j = 0; j < 128; j++)
                a0 = fmaf(sRi[(j << 2) + f], sG[j * 21 + c], a0);
            sB[f * 100 + chunk * 20 + c] = a0;
        }
        __syncthreads();
    }

    // DR[m][h] = sum_f tmpB[f][m]*tmpB[f][h], m<16, h<100
#pragma unroll 1
    for (int o = tid; o < DRDIM; o += 128) {
        int m = o / 100, h = o - m * 100;
        float d = sB[m]       * sB[h]
                + sB[100 + m] * sB[100 + h]
                + sB[200 + m] * sB[200 + h]
                + sB[300 + m] * sB[300 + h];
        g_DR[atom * DRDIM + o] = d;
    }
}

// ---------------- tiled fp32 GEMM: C = act(A(M,K) @ W(K,N) + b) -------------
template<bool ACT>
__global__ __launch_bounds__(256) void gemm_kernel(
    const float* __restrict__ A, const float* __restrict__ W,
    const float* __restrict__ bias, float* __restrict__ C,
    int M, int N, int K)
{
    const int BM = 64, BN = 64, BK = 16;
    __shared__ float As[BK][BM];
    __shared__ float Ws[BK][BN];

    int tid = threadIdx.x;
    int bm = blockIdx.y * BM;
    int bn = blockIdx.x * BN;
    int ty = tid / 16, tx = tid % 16;

    float acc[4][4];
#pragma unroll
    for (int i = 0; i < 4; i++)
#pragma unroll
        for (int j = 0; j < 4; j++) acc[i][j] = 0.0f;

    int arow = tid >> 2;             // 0..63
    int akq  = (tid & 3) * 4;        // 0,4,8,12
    int wrow = tid >> 4;             // 0..15
    int wnq  = (tid & 15) * 4;       // 0..60

    const float* Ag = A + (bm + arow) * K + akq;
    const float* Wg = W + wrow * N + bn + wnq;
    bool wvalid = (bn + wnq) < N;

    for (int k0 = 0; k0 < K; k0 += BK) {
        float4 av = *reinterpret_cast<const float4*>(Ag + k0);
        float4 wv = wvalid ? *reinterpret_cast<const float4*>(Wg + k0 * N)
                           : make_float4(0.f, 0.f, 0.f, 0.f);
        __syncthreads();
        As[akq + 0][arow] = av.x;
        As[akq + 1][arow] = av.y;
        As[akq + 2][arow] = av.z;
        As[akq + 3][arow] = av.w;
        *reinterpret_cast<float4*>(&Ws[wrow][wnq]) = wv;
        __syncthreads();
#pragma unroll
        for (int k = 0; k < BK; k++) {
            float4 a = *reinterpret_cast<const float4*>(&As[k][ty * 4]);
            float4 w = *reinterpret_cast<const float4*>(&Ws[k][tx * 4]);
            float avr[4] = {a.x, a.y, a.z, a.w};
            float wvr[4] = {w.x, w.y, w.z, w.w};
#pragma unroll
            for (int i = 0; i < 4; i++)
#pragma unroll
                for (int j = 0; j < 4; j++)
                    acc[i][j] = fmaf(avr[i], wvr[j], acc[i][j]);
        }
    }

    int col = bn + tx * 4;
    if (col < N) {
        float b0 = bias[col + 0], b1 = bias[col + 1], b2 = bias[col + 2], b3 = bias[col + 3];
#pragma unroll
        for (int i = 0; i < 4; i++) {
            int row = bm + ty * 4 + i;
            float4 r;
            r.x = acc[i][0] + b0;
            r.y = acc[i][1] + b1;
            r.z = acc[i][2] + b2;
            r.w = acc[i][3] + b3;
            if (ACT) {
                r.x = tanhfast(r.x); r.y = tanhfast(r.y);
                r.z = tanhfast(r.z); r.w = tanhfast(r.w);
            }
            *reinterpret_cast<float4*>(&C[row * N + col]) = r;
        }
    }
}

// ---------------- Ei = H3 @ fw3 + fb3 (one warp per atom) ----------------
__global__ __launch_bounds__(256) void ei_kernel(
    const float* __restrict__ H3, const float* __restrict__ fw3,
    const float* __restrict__ fb3, float* __restrict__ out)
{
    int gw = (blockIdx.x * blockDim.x + threadIdx.x) >> 5;
    int lane = threadIdx.x & 31;
    if (gw >= ATOMS) return;
    const float* row = H3 + gw * F0;
    float a = 0.0f;
#pragma unroll
    for (int i = lane; i < F0; i += 32) a = fmaf(row[i], fw3[i], a);
#pragma unroll
    for (int off = 16; off; off >>= 1) a += __shfl_xor_sync(0xFFFFFFFFu, a, off);
    if (lane == 0) out[8 + gw] = a + fb3[0];
}

// ---------------- Etot[b] = sum_n Ei[b,n] ----------------
__global__ __launch_bounds__(128) void etot_kernel(float* __restrict__ out)
{
    __shared__ float red[4];
    int b = blockIdx.x;
    int tid = threadIdx.x;
    float a = 0.0f;
    for (int i = tid; i < N_; i += 128) a += out[8 + b * N_ + i];
#pragma unroll
    for (int off = 16; off; off >>= 1) a += __shfl_xor_sync(0xFFFFFFFFu, a, off);
    if ((tid & 31) == 0) red[tid >> 5] = a;
    __syncthreads();
    if (tid == 0) out[b] = red[0] + red[1] + red[2] + red[3];
}

// ---------------- launch ----------------
extern "C" void kernel_launch(void* const* d_in, const int* in_sizes, int n_in,
                              void* d_out, int out_size)
{
    const float* img = (const float*)d_in[0];
    const float* ew0 = (const float*)d_in[1];
    const float* eb0 = (const float*)d_in[2];
    const float* ew1 = (const float*)d_in[3];
    const float* eb1 = (const float*)d_in[4];
    const float* ew2 = (const float*)d_in[5];
    const float* eb2 = (const float*)d_in[6];
    const float* fw0 = (const float*)d_in[7];
    const float* fb0 = (const float*)d_in[8];
    const float* fw1 = (const float*)d_in[9];
    const float* fb1 = (const float*)d_in[10];
    const float* fw2 = (const float*)d_in[11];
    const float* fb2 = (const float*)d_in[12];
    const float* fw3 = (const float*)d_in[13];
    const float* fb3 = (const float*)d_in[14];
    float* out = (float*)d_out;

    void *pDR, *pH1, *pH2, *pH3;
    cudaGetSymbolAddress(&pDR, g_DR);
    cudaGetSymbolAddress(&pH1, g_H1);
    cudaGetSymbolAddress(&pH2, g_H2);
    cudaGetSymbolAddress(&pH3, g_H3);

    embed_kernel<<<ATOMS, 128>>>((const float4*)img, ew0, eb0, ew1, eb1, ew2, eb2);

    gemm_kernel<true><<<dim3(4, ATOMS / 64), 256>>>(
        (const float*)pDR, fw0, fb0, (float*)pH1, ATOMS, F0, DRDIM);
    gemm_kernel<true><<<dim3(4, ATOMS / 64), 256>>>(
        (const float*)pH1, fw1, fb1, (float*)pH2, ATOMS, F0, F0);
    gemm_kernel<true><<<dim3(4, ATOMS / 64), 256>>>(
        (const float*)pH2, fw2, fb2, (float*)pH3, ATOMS, F0, F0);

    ei_kernel<<<(ATOMS * 32 + 255) / 256, 256>>>((const float*)pH3, fw3, fb3, out);
    etot_kernel<<<B_, 128>>>(out);
}

// round 3
// speedup vs baseline: 1.3220x; 1.3220x over previous
#include <cuda_runtime.h>
#include <math.h>

#define B_    8
#define N_    512
#define KN    128
#define ATOMS 4096      // B_*N_
#define DRDIM 1600
#define F0    240
#define NTAB  512
#define SMAXF 1.3335f   // S = 1/R <= 1/0.75 = 1.3333...

// ---------------- scratch (no allocations allowed) ----------------
__device__ float g_DR[ATOMS * DRDIM];            // 26 MB
__device__ float g_P [4 * ATOMS * F0];           // split-K partials, 15.7 MB
__device__ float g_H1[ATOMS * F0];
__device__ float g_H2[ATOMS * F0];
__device__ float g_H3[ATOMS * F0];
__device__ float g_tab[(NTAB + 1) * 100];        // G(S) lookup table

// fast, accurate-enough tanh: 1 - 2/(1+exp(2x)); abs err ~1e-7
__device__ __forceinline__ float tanhfast(float x) {
    float e = __expf(2.0f * x);
    return 1.0f - __fdividef(2.0f, e + 1.0f);
}

// ---------------- kernel 0: build G(S) table (513 nodes) ----------------
__global__ __launch_bounds__(128) void build_tab_kernel(
    const float* __restrict__ ew0, const float* __restrict__ eb0,
    const float* __restrict__ ew1, const float* __restrict__ eb1,
    const float* __restrict__ ew2, const float* __restrict__ eb2)
{
    int i = blockIdx.x * 128 + threadIdx.x;
    if (i > NTAB) return;
    float S = (float)i * (SMAXF / (float)NTAB);

    float h1[25];
#pragma unroll
    for (int k = 0; k < 25; k++)
        h1[k] = tanhfast(fmaf(S, __ldg(&ew0[k]), __ldg(&eb0[k])));

    float h2[50];
#pragma unroll
    for (int k = 0; k < 50; k++) h2[k] = __ldg(&eb1[k]);
#pragma unroll
    for (int q = 0; q < 25; q++) {
        float a = h1[q];
#pragma unroll
        for (int k = 0; k < 50; k++) h2[k] = fmaf(a, __ldg(&ew1[q * 50 + k]), h2[k]);
    }
#pragma unroll
    for (int k = 0; k < 50; k++) h2[k] = tanhfast(h2[k]);

    // 100 outputs in 2 chunks of 50 to bound registers
#pragma unroll 1
    for (int c = 0; c < 2; c++) {
        float g[50];
#pragma unroll
        for (int k = 0; k < 50; k++) g[k] = __ldg(&eb2[c * 50 + k]);
#pragma unroll 1
        for (int q = 0; q < 50; q++) {
            float a = h2[q];
#pragma unroll
            for (int k = 0; k < 50; k++)
                g[k] = fmaf(a, __ldg(&ew2[q * 100 + c * 50 + k]), g[k]);
        }
#pragma unroll
        for (int k = 0; k < 50; k++) g_tab[i * 100 + c * 50 + k] = tanhfast(g[k]);
    }
}

// ---------------- kernel 1: per-atom geometry + table interp + DR ----------
// block = 1 atom, 128 threads = 128 neighbors
__global__ __launch_bounds__(128) void embed_kernel(const float4* __restrict__ img)
{
    __shared__ float sRi[128 * 4];
    __shared__ float sG[128 * 21];        // 20 G-cols per chunk, pad 21
    __shared__ float sB[400];             // tmpB [4][100]

    const int tid = threadIdx.x;
    const int atom = blockIdx.x;

    // per-neighbor geometry
    float4 p = img[atom * KN + tid];
    float R = p.x * p.x + p.y * p.y + p.z * p.z;
    bool mask = p.w > 0.0f;
    float S = 0.0f;
    if (R < 10.0f) {
        if (mask) S = 1.0f / R;
    } else if (R < 25.0f) {
        // reference's b2 branch does NOT require mask
        S = 0.5f * cosf(0.20943951023931953f * (R - 10.0f)) + 0.5f;
    }
    float coef = mask ? S / R : 0.0f;
    sRi[tid * 4 + 0] = S;
    sRi[tid * 4 + 1] = coef * p.x;
    sRi[tid * 4 + 2] = coef * p.y;
    sRi[tid * 4 + 3] = coef * p.z;

    // table position
    float t = S * ((float)NTAB / SMAXF);
    int idx = (int)t;
    if (idx > NTAB - 1) idx = NTAB - 1;
    float frac = t - (float)idx;
    const float4* r0 = reinterpret_cast<const float4*>(g_tab + idx * 100);
    const float4* r1 = reinterpret_cast<const float4*>(g_tab + (idx + 1) * 100);
    __syncthreads();

    // 5 chunks of 20 G-columns; interp + tmpB reduction per chunk
#pragma unroll 1
    for (int chunk = 0; chunk < 5; chunk++) {
#pragma unroll
        for (int q = 0; q < 5; q++) {
            float4 a = __ldg(&r0[chunk * 5 + q]);
            float4 b = __ldg(&r1[chunk * 5 + q]);
            sG[tid * 21 + q * 4 + 0] = fmaf(frac, b.x - a.x, a.x);
            sG[tid * 21 + q * 4 + 1] = fmaf(frac, b.y - a.y, a.y);
            sG[tid * 21 + q * 4 + 2] = fmaf(frac, b.z - a.z, a.z);
            sG[tid * 21 + q * 4 + 3] = fmaf(frac, b.w - a.w, a.w);
        }
        __syncthreads();

        // tmpB[f][chunk*20+c] = sum_j Ri[j][f] * G[j][c]
        if (tid < 80) {
            int f = tid / 20, c = tid - f * 20;
            float a0 = 0.0f;
#pragma unroll 4
            for (int j = 0; j < 128; j++)
                a0 = fmaf(sRi[(j << 2) + f], sG[j * 21 + c], a0);
            sB[f * 100 + chunk * 20 + c] = a0;
        }
        __syncthreads();
    }

    // DR[m][h] = sum_f tmpB[f][m]*tmpB[f][h], m<16, h<100
#pragma unroll 1
    for (int o = tid; o < DRDIM; o += 128) {
        int m = o / 100, h = o - m * 100;
        float d = sB[m]       * sB[h]
                + sB[100 + m] * sB[100 + h]
                + sB[200 + m] * sB[200 + h]
                + sB[300 + m] * sB[300 + h];
        g_DR[atom * DRDIM + o] = d;
    }
}

// ---------------- fp32 GEMM: BM=64 BN=80 BK=16, 256 thr, 4x5 micro ---------
// SPLITK>1: writes raw partial to C + z*M*N (no bias/act).
// SPLITK==1: writes act(acc + bias).
template<int SPLITK, bool ACT>
__global__ __launch_bounds__(256) void gemm_kernel(
    const float* __restrict__ A, const float* __restrict__ W,
    const float* __restrict__ bias, float* __restrict__ C,
    int M, int N, int K)
{
    const int BM = 64, BN = 80, BK = 16;
    __shared__ float As[BK * 68];   // [k][m], padded row 68
    __shared__ float Ws[BK * BN];   // [k][n]

    int tid = threadIdx.x;
    int bm = blockIdx.y * BM;
    int bn = blockIdx.x * BN;
    int kz = (SPLITK > 1) ? blockIdx.z : 0;
    int klen = K / SPLITK;
    int kbeg = kz * klen;

    int ty = tid / 16;              // 0..15 -> 4 rows each
    int tx = tid - ty * 16;         // 0..15 -> 5 cols each

    float acc[4][5];
#pragma unroll
    for (int i = 0; i < 4; i++)
#pragma unroll
        for (int j = 0; j < 5; j++) acc[i][j] = 0.0f;

    int arow = tid >> 2;            // 0..63
    int akq  = (tid & 3) * 4;       // 0,4,8,12
    const float* Ag = A + (bm + arow) * K + akq + kbeg;

    for (int k0 = 0; k0 < klen; k0 += BK) {
        float4 av = *reinterpret_cast<const float4*>(Ag + k0);
        // W tile: 16x80 = 320 float4
        float4 wv0, wv1;
        {
            int r = tid / 20, c4 = tid - r * 20;
            wv0 = *reinterpret_cast<const float4*>(W + (kbeg + k0 + r) * N + bn + c4 * 4);
        }
        int idx1 = 256 + tid;
        int r1 = idx1 / 20, c41 = idx1 - r1 * 20;
        if (tid < 64)
            wv1 = *reinterpret_cast<const float4*>(W + (kbeg + k0 + r1) * N + bn + c41 * 4);
        __syncthreads();
        As[(akq + 0) * 68 + arow] = av.x;
        As[(akq + 1) * 68 + arow] = av.y;
        As[(akq + 2) * 68 + arow] = av.z;
        As[(akq + 3) * 68 + arow] = av.w;
        {
            int r = tid / 20, c4 = tid - r * 20;
            *reinterpret_cast<float4*>(&Ws[r * BN + c4 * 4]) = wv0;
        }
        if (tid < 64)
            *reinterpret_cast<float4*>(&Ws[r1 * BN + c41 * 4]) = wv1;
        __syncthreads();

#pragma unroll
        for (int k = 0; k < BK; k++) {
            float4 a = *reinterpret_cast<const float4*>(&As[k * 68 + ty * 4]);
            float w0 = Ws[k * BN + tx * 5 + 0];
            float w1 = Ws[k * BN + tx * 5 + 1];
            float w2 = Ws[k * BN + tx * 5 + 2];
            float w3 = Ws[k * BN + tx * 5 + 3];
            float w4 = Ws[k * BN + tx * 5 + 4];
            float ar[4] = {a.x, a.y, a.z, a.w};
#pragma unroll
            for (int i = 0; i < 4; i++) {
                acc[i][0] = fmaf(ar[i], w0, acc[i][0]);
                acc[i][1] = fmaf(ar[i], w1, acc[i][1]);
                acc[i][2] = fmaf(ar[i], w2, acc[i][2]);
                acc[i][3] = fmaf(ar[i], w3, acc[i][3]);
                acc[i][4] = fmaf(ar[i], w4, acc[i][4]);
            }
        }
    }

    float* Cout = C + (size_t)kz * M * N;
    int col = bn + tx * 5;
    float b0 = 0.f, b1 = 0.f, b2 = 0.f, b3 = 0.f, b4 = 0.f;
    if (SPLITK == 1) {
        b0 = bias[col + 0]; b1 = bias[col + 1]; b2 = bias[col + 2];
        b3 = bias[col + 3]; b4 = bias[col + 4];
    }
#pragma unroll
    for (int i = 0; i < 4; i++) {
        int row = bm + ty * 4 + i;
        float v0 = acc[i][0] + b0;
        float v1 = acc[i][1] + b1;
        float v2 = acc[i][2] + b2;
        float v3 = acc[i][3] + b3;
        float v4 = acc[i][4] + b4;
        if (ACT) {
            v0 = tanhfast(v0); v1 = tanhfast(v1); v2 = tanhfast(v2);
            v3 = tanhfast(v3); v4 = tanhfast(v4);
        }
        float* cr = Cout + (size_t)row * N + col;
        cr[0] = v0; cr[1] = v1; cr[2] = v2; cr[3] = v3; cr[4] = v4;
    }
}

// ---------------- split-K epilogue: H1 = tanh(sum_z P_z + bias) ------------
__global__ __launch_bounds__(256) void splitk_epi_kernel(
    const float* __restrict__ P, const float* __restrict__ bias,
    float* __restrict__ H)
{
    const int MN = ATOMS * F0;
    int i = blockIdx.x * 256 + threadIdx.x;
    if (i >= MN) return;
    int col = i % F0;
    float s = P[i] + P[i + MN] + P[i + 2 * MN] + P[i + 3 * MN] + bias[col];
    H[i] = tanhfast(s);
}

// ---------------- Ei = H3 @ fw3 + fb3 (one warp per atom) ----------------
__global__ __launch_bounds__(256) void ei_kernel(
    const float* __restrict__ H3, const float* __restrict__ fw3,
    const float* __restrict__ fb3, float* __restrict__ out)
{
    int gw = (blockIdx.x * blockDim.x + threadIdx.x) >> 5;
    int lane = threadIdx.x & 31;
    if (gw >= ATOMS) return;
    const float* row = H3 + gw * F0;
    float a = 0.0f;
#pragma unroll
    for (int i = lane; i < F0; i += 32) a = fmaf(row[i], fw3[i], a);
#pragma unroll
    for (int off = 16; off; off >>= 1) a += __shfl_xor_sync(0xFFFFFFFFu, a, off);
    if (lane == 0) out[8 + gw] = a + fb3[0];
}

// ---------------- Etot[b] = sum_n Ei[b,n] ----------------
__global__ __launch_bounds__(128) void etot_kernel(float* __restrict__ out)
{
    __shared__ float red[4];
    int b = blockIdx.x;
    int tid = threadIdx.x;
    float a = 0.0f;
    for (int i = tid; i < N_; i += 128) a += out[8 + b * N_ + i];
#pragma unroll
    for (int off = 16; off; off >>= 1) a += __shfl_xor_sync(0xFFFFFFFFu, a, off);
    if ((tid & 31) == 0) red[tid >> 5] = a;
    __syncthreads();
    if (tid == 0) out[b] = red[0] + red[1] + red[2] + red[3];
}

// ---------------- launch ----------------
extern "C" void kernel_launch(void* const* d_in, const int* in_sizes, int n_in,
                              void* d_out, int out_size)
{
    const float* img = (const float*)d_in[0];
    const float* ew0 = (const float*)d_in[1];
    const float* eb0 = (const float*)d_in[2];
    const float* ew1 = (const float*)d_in[3];
    const float* eb1 = (const float*)d_in[4];
    const float* ew2 = (const float*)d_in[5];
    const float* eb2 = (const float*)d_in[6];
    const float* fw0 = (const float*)d_in[7];
    const float* fb0 = (const float*)d_in[8];
    const float* fw1 = (const float*)d_in[9];
    const float* fb1 = (const float*)d_in[10];
    const float* fw2 = (const float*)d_in[11];
    const float* fb2 = (const float*)d_in[12];
    const float* fw3 = (const float*)d_in[13];
    const float* fb3 = (const float*)d_in[14];
    float* out = (float*)d_out;

    void *pDR, *pP, *pH1, *pH2, *pH3;
    cudaGetSymbolAddress(&pDR, g_DR);
    cudaGetSymbolAddress(&pP,  g_P);
    cudaGetSymbolAddress(&pH1, g_H1);
    cudaGetSymbolAddress(&pH2, g_H2);
    cudaGetSymbolAddress(&pH3, g_H3);

    build_tab_kernel<<<(NTAB + 1 + 127) / 128, 128>>>(ew0, eb0, ew1, eb1, ew2, eb2);
    embed_kernel<<<ATOMS, 128>>>((const float4*)img);

    // GEMM1: DR(4096x1600) @ fw0(1600x240), split-K=4 -> partials, then epilogue
    gemm_kernel<4, false><<<dim3(3, ATOMS / 64, 4), 256>>>(
        (const float*)pDR, fw0, nullptr, (float*)pP, ATOMS, F0, DRDIM);
    splitk_epi_kernel<<<(ATOMS * F0 + 255) / 256, 256>>>(
        (const float*)pP, fb0, (float*)pH1);

    gemm_kernel<1, true><<<dim3(3, ATOMS / 64, 1), 256>>>(
        (const float*)pH1, fw1, fb1, (float*)pH2, ATOMS, F0, F0);
    gemm_kernel<1, true><<<dim3(3, ATOMS / 64, 1), 256>>>(
        (const float*)pH2, fw2, fb2, (float*)pH3, ATOMS, F0, F0);

    ei_kernel<<<(ATOMS * 32 + 255) / 256, 256>>>((const float*)pH3, fw3, fb3, out);
    etot_kernel<<<B_, 128>>>(out);
}